// round 7
// baseline (speedup 1.0000x reference)
#include <cuda_runtime.h>

typedef unsigned long long u64t;

#define BB 8
#define TT 100
#define UU 64
#define ZZ 256   // 4U
#define PP 1000
#define NK 50
#define NKP 56   // padded row: [0..24]=k0..24, [25..27]=0, [28..52]=k25..49, [53..55]=0
#define BT (BB*TT) // 800

#define NB_GEMM 104
#define NB_XW   125
#define NB_LSTM 8
#define NB_MAIN 64
#define NB_TOT  (NB_GEMM + NB_XW + NB_LSTM + NB_MAIN)   // 301

// Scratch (__device__ globals — no allocation)
__device__ __align__(16) float d_xk[BT*ZZ];
__device__ __align__(16) float d_g[BB*TT*NKP];
__device__ __align__(16) float d_XW[1024*NKP];

// dataflow flags (self-resetting across graph replays)
__device__ int f_xk   = 0;   // GEMM blocks done  (target 104)
__device__ int f_xw   = 0;   // XW blocks done    (target 125)
__device__ int f_g    = 0;   // LSTM blocks done  (target 8)
__device__ int f_done = 0;   // MAIN blocks done  (target 64) -> resets all

// ---- packed f32x2 helpers ---------------------------------------------------
__device__ __forceinline__ u64t f2pk(float lo, float hi) {
    u64t r; asm("mov.b64 %0,{%1,%2};" : "=l"(r) : "f"(lo), "f"(hi)); return r;
}
__device__ __forceinline__ u64t ffma2(u64t a, u64t b, u64t c) {
    u64t d; asm("fma.rn.f32x2 %0,%1,%2,%3;" : "=l"(d) : "l"(a), "l"(b), "l"(c)); return d;
}
__device__ __forceinline__ u64t fadd2(u64t a, u64t b) {
    u64t d; asm("add.rn.f32x2 %0,%1,%2;" : "=l"(d) : "l"(a), "l"(b)); return d;
}
__device__ __forceinline__ float2 f2up(u64t v) {
    float2 r; asm("mov.b64 {%0,%1},%2;" : "=f"(r.x), "=f"(r.y) : "l"(v)); return r;
}
__device__ __forceinline__ float sigf(float x) {
    return __fdividef(1.f, 1.f + __expf(-x));
}
__device__ __forceinline__ float tanhfast(float x) {
    return 1.f - __fdividef(2.f, __expf(2.f*x) + 1.f);
}
__device__ __forceinline__ int padpos(int k) { return (k < 25) ? k : k + 3; }

// ---- sync primitives --------------------------------------------------------
__device__ __forceinline__ void signal(int* flag) {
    // publish this block's global writes, then release-increment
    __threadfence();
    __syncthreads();
    if (threadIdx.x == 0)
        asm volatile("red.release.gpu.global.add.s32 [%0], 1;" :: "l"(flag) : "memory");
}
__device__ __forceinline__ int ld_acq(int* p) {
    int v; asm volatile("ld.acquire.gpu.global.s32 %0, [%1];" : "=r"(v) : "l"(p) : "memory");
    return v;
}
__device__ __forceinline__ void wait_ge(int* flag, int target) {
    if (threadIdx.x == 0) {
        while (ld_acq(flag) < target) __nanosleep(100);
    }
    __syncthreads();
}

// shared-memory union (30.0 KB max -> static smem OK)
union SmemU {
    struct { float A[32][64]; float B[32][32]; } g;        // 12 KB  (GEMM)
    struct { float W[128*52]; float Xr[8][128]; } w;       // 30 KB  (XW)
    struct { float h[TT][UU]; float a[ZZ]; } l;            // 26 KB  (LSTM)
    struct { float gsh[TT*NKP]; int pid[TT]; } m;          // 22.7KB (MAIN)
};

// ===========================================================================
__global__ void __launch_bounds__(256) k_all(
    const int* __restrict__ pro_id, const int* __restrict__ label,
    const float* __restrict__ X, const float* __restrict__ cosX,
    const float* __restrict__ onehot, const float* __restrict__ Kmat,
    const float* __restrict__ rec, const float* __restrict__ bias,
    const float* __restrict__ W1, const float* __restrict__ b1,
    const float* __restrict__ W2, const float* __restrict__ b2,
    float* __restrict__ out) {
    __shared__ SmemU sh;
    int tid = threadIdx.x;
    int bx = blockIdx.x;

    if (bx < NB_GEMM) {
        // ================= xk GEMM: 64x32 tile, K=256 ======================
        int mblk = bx % 13, nblk = bx / 13;
        int rowBase = mblk * 64;
        int n0 = nblk * 32;
        int ty = tid >> 4, tx = tid & 15;

        // hoisted per-thread staging state (two 32-row sub-tiles)
        int m0 = tid >> 3;            // 0..31
        int kq = (tid & 7) * 4;       // 0..28
        int row0 = rowBase + m0, row1 = rowBase + m0 + 32;
        bool v0 = row0 < BT, v1 = row1 < BT;
        const float *xp0 = 0, *op0 = 0, *xp1 = 0, *op1 = 0;
        if (v0) { xp0 = X + pro_id[row0]*128; op0 = onehot + label[row0]*ZZ; }
        if (v1) { xp1 = X + pro_id[row1]*128; op1 = onehot + label[row1]*ZZ; }

        u64t acc2[2][2] = {{0ull,0ull},{0ull,0ull}};

        for (int k0 = 0; k0 < 256; k0 += 32) {
            int i0 = k0 + kq;
            {
                float4 v = make_float4(0.f,0.f,0.f,0.f);
                if (v0) {
                    float4 xv = *(const float4*)&xp0[i0 & 127];
                    float4 ov = *(const float4*)&op0[i0];
                    v = make_float4(xv.x*ov.x, xv.y*ov.y, xv.z*ov.z, xv.w*ov.w);
                }
                sh.g.A[kq+0][m0] = v.x; sh.g.A[kq+1][m0] = v.y;
                sh.g.A[kq+2][m0] = v.z; sh.g.A[kq+3][m0] = v.w;
            }
            {
                float4 v = make_float4(0.f,0.f,0.f,0.f);
                if (v1) {
                    float4 xv = *(const float4*)&xp1[i0 & 127];
                    float4 ov = *(const float4*)&op1[i0];
                    v = make_float4(xv.x*ov.x, xv.y*ov.y, xv.z*ov.z, xv.w*ov.w);
                }
                sh.g.A[kq+0][m0+32] = v.x; sh.g.A[kq+1][m0+32] = v.y;
                sh.g.A[kq+2][m0+32] = v.z; sh.g.A[kq+3][m0+32] = v.w;
            }
            {   // plain B tile 32x32 (one float4 per thread)
                int kk = tid >> 3;
                int n4 = (tid & 7) * 4;
                *(float4*)&sh.g.B[kk][n4] = *(const float4*)&Kmat[(k0 + kk)*256 + n0 + n4];
            }
            __syncthreads();
#pragma unroll
            for (int kk = 0; kk < 32; ++kk) {
                longlong2 av = *(const longlong2*)&sh.g.A[kk][ty*4];
                float2 bv = *(const float2*)&sh.g.B[kk][tx*2];
                u64t bx0 = f2pk(bv.x, bv.x);
                u64t bx1 = f2pk(bv.y, bv.y);
                acc2[0][0] = ffma2((u64t)av.x, bx0, acc2[0][0]);
                acc2[1][0] = ffma2((u64t)av.y, bx0, acc2[1][0]);
                acc2[0][1] = ffma2((u64t)av.x, bx1, acc2[0][1]);
                acc2[1][1] = ffma2((u64t)av.y, bx1, acc2[1][1]);
            }
            __syncthreads();
        }
        float bs0 = __ldg(&bias[n0 + tx*2]);
        float bs1 = __ldg(&bias[n0 + tx*2 + 1]);
#pragma unroll
        for (int mp = 0; mp < 2; ++mp) {
            float2 c0 = f2up(acc2[mp][0]);
            float2 c1 = f2up(acc2[mp][1]);
            int r0 = rowBase + ty*4 + 2*mp;
            if (r0 < BT) {
                d_xk[r0*ZZ + n0 + tx*2]     = c0.x + bs0;
                d_xk[r0*ZZ + n0 + tx*2 + 1] = c1.x + bs1;
            }
            if (r0 + 1 < BT) {
                d_xk[(r0+1)*ZZ + n0 + tx*2]     = c0.y + bs0;
                d_xk[(r0+1)*ZZ + n0 + tx*2 + 1] = c1.y + bs1;
            }
        }
        signal(&f_xk);

    } else if (bx < NB_GEMM + NB_XW) {
        // ================= XW: 8 p per block, staged W1b ===================
        int pbase = (bx - NB_GEMM) * 8;
        for (int idx = tid; idx < 128*NK; idx += 256) {
            int j = idx / NK, k = idx - j*NK;
            sh.w.W[j*52 + k] = __ldg(&W1[(64 + j)*NK + k]);
        }
        {
            int pl = tid >> 5, quad = tid & 31;
            ((float4*)sh.w.Xr[pl])[quad] = *(const float4*)&X[(pbase + pl)*128 + quad*4];
        }
        __syncthreads();

        int pl = tid >> 5, lane = tid & 31;
        int p = pbase + pl;
        if (lane < 25) {
            int k2 = lane * 2;
            u64t acc = f2pk(__ldg(&b1[k2]), __ldg(&b1[k2+1]));
            const float* xr = sh.w.Xr[pl];
#pragma unroll 8
            for (int j = 0; j < 128; ++j) {
                float x = xr[j];
                acc = ffma2(f2pk(x, x), *(const u64t*)&sh.w.W[j*52 + k2], acc);
            }
            float2 r = f2up(acc);
            d_XW[p*NKP + padpos(k2)]     = r.x;
            d_XW[p*NKP + padpos(k2 + 1)] = r.y;
        } else if (lane < 31) {
            int off = (lane <= 27) ? lane : lane + 25;
            d_XW[p*NKP + off] = 0.f;
        }
        signal(&f_xw);

    } else if (bx < NB_GEMM + NB_XW + NB_LSTM) {
        // ================= LSTM recurrence + g epilogue ====================
        int b = bx - (NB_GEMM + NB_XW);
        int j = tid;

        u64t rc2[32];
#pragma unroll
        for (int m = 0; m < 32; ++m)
            rc2[m] = f2pk(rec[(2*m)*ZZ + j], rec[(2*m+1)*ZZ + j]);

        int grp = j >> 6;
        float c = 0.f;

        wait_ge(&f_xk, NB_GEMM);

        float xk_next = d_xk[(b*TT)*ZZ + j];
#pragma unroll 1
        for (int t = 0; t < TT; ++t) {
            float xk = xk_next;
            if (t + 1 < TT) xk_next = d_xk[(b*TT + t + 1)*ZZ + j];
            float z;
            if (t == 0) {
                z = xk;
            } else {
                const longlong2* h8 = (const longlong2*)sh.l.h[t-1];
                u64t z0 = f2pk(xk, 0.f), z1 = 0ull, z2 = 0ull, z3 = 0ull;
#pragma unroll
                for (int i = 0; i < 8; ++i) {
                    longlong2 hA = h8[i], hB = h8[i+8];
                    z0 = ffma2((u64t)hA.x, rc2[2*i],    z0);
                    z1 = ffma2((u64t)hA.y, rc2[2*i+1],  z1);
                    z2 = ffma2((u64t)hB.x, rc2[2*i+16], z2);
                    z3 = ffma2((u64t)hB.y, rc2[2*i+17], z3);
                }
                float2 r = f2up(fadd2(fadd2(z0, z1), fadd2(z2, z3)));
                z = r.x + r.y;
            }
            sh.l.a[j] = (grp == 2) ? tanhfast(z) : sigf(z);
            __syncthreads();
            if (j < UU) {
                float ai = sh.l.a[j], af = sh.l.a[64+j], ag = sh.l.a[128+j], ao = sh.l.a[192+j];
                c = fmaf(af, c, ai*ag);
                sh.l.h[t][j] = ao * tanhfast(c);
            }
            __syncthreads();
        }

        // g[b,t,k] = sum_u h[t][u] * W1[u*50+k]
        int k = j & 63, tc = j >> 6;
        if (k < NK) {
            u64t w1c[32];
#pragma unroll
            for (int m = 0; m < 32; ++m)
                w1c[m] = f2pk(__ldg(&W1[(2*m)*NK + k]), __ldg(&W1[(2*m+1)*NK + k]));
            int off = padpos(k);
#pragma unroll 1
            for (int tt = tc*25; tt < tc*25 + 25; ++tt) {
                const longlong2* h8 = (const longlong2*)sh.l.h[tt];
                u64t g0 = 0ull, g1 = 0ull, g2 = 0ull, g3 = 0ull;
#pragma unroll
                for (int i = 0; i < 8; ++i) {
                    longlong2 hA = h8[i], hB = h8[i+8];
                    g0 = ffma2((u64t)hA.x, w1c[2*i],    g0);
                    g1 = ffma2((u64t)hA.y, w1c[2*i+1],  g1);
                    g2 = ffma2((u64t)hB.x, w1c[2*i+16], g2);
                    g3 = ffma2((u64t)hB.y, w1c[2*i+17], g3);
                }
                float2 r = f2up(fadd2(fadd2(g0, g1), fadd2(g2, g3)));
                d_g[(b*TT + tt)*NKP + off] = r.x + r.y;
            }
        } else if (k < 56) {
            int off = (k >= 53) ? k : (k - 25);
            for (int tt = tc*25; tt < tc*25 + 25; ++tt)
                d_g[(b*TT + tt)*NKP + off] = 0.f;
        }
        signal(&f_g);

    } else {
        // ================= MAIN: 128 p x 2-way k-split =====================
        int idx = bx - (NB_GEMM + NB_XW + NB_LSTM);   // 0..63
        int b = idx >> 3;
        int pchunk = idx & 7;

        // pre-spin staging (inputs only): pid, W2, b2, first cosX
        for (int t = tid; t < TT; t += 256) sh.m.pid[t] = pro_id[b*TT + t];
        __syncthreads();

        int p    = pchunk*128 + (tid >> 1);
        int half = tid & 1;
        bool valid = (p < PP);
        int pc = valid ? p : (PP - 1);

        float w2r[28];
#pragma unroll
        for (int jj = 0; jj < 28; ++jj)
            w2r[jj] = (jj < 25) ? __ldg(&W2[half*25 + jj]) : 0.f;
        float b2v = __ldg(b2);
        float av = __ldg(&cosX[sh.m.pid[TT-1]*PP + pc]);

        // wait for g and XW
        if (tid == 0) {
            while (ld_acq(&f_g) < NB_LSTM || ld_acq(&f_xw) < NB_XW) __nanosleep(100);
        }
        __syncthreads();

        // stage g for this batch
        {
            const float4* gg = (const float4*)&d_g[b*TT*NKP];
            float4* gs = (float4*)sh.m.gsh;
            for (int i = tid; i < (TT*NKP)/4; i += 256) gs[i] = gg[i];
        }
        __syncthreads();

        float acc[28];
        {
            const float2* x2 = (const float2*)&d_XW[p*NKP + half*28];
#pragma unroll
            for (int m = 0; m < 14; ++m) { float2 v = x2[m]; acc[2*m] = v.x; acc[2*m+1] = v.y; }
        }

#pragma unroll 1
        for (int t = TT - 1; t >= 0; --t) {
            float avn = (t > 0) ? __ldg(&cosX[sh.m.pid[t-1]*PP + pc]) : 0.f;
            const float4* g4 = (const float4*)&sh.m.gsh[t*NKP + half*28];
#pragma unroll
            for (int m = 0; m < 7; ++m) {
                float4 gv = g4[m];
                acc[4*m]   = fmaf(av, gv.x, acc[4*m]);
                acc[4*m+1] = fmaf(av, gv.y, acc[4*m+1]);
                acc[4*m+2] = fmaf(av, gv.z, acc[4*m+2]);
                acc[4*m+3] = fmaf(av, gv.w, acc[4*m+3]);
            }
            float d0 = 0.f, d1 = 0.f, d2 = 0.f, d3 = 0.f;
#pragma unroll
            for (int jj = 0; jj < 28; jj += 4) {
                d0 = fmaf(fmaxf(acc[jj],   0.f), w2r[jj],   d0);
                d1 = fmaf(fmaxf(acc[jj+1], 0.f), w2r[jj+1], d1);
                d2 = fmaf(fmaxf(acc[jj+2], 0.f), w2r[jj+2], d2);
                d3 = fmaf(fmaxf(acc[jj+3], 0.f), w2r[jj+3], d3);
            }
            float d = (d0 + d1) + (d2 + d3);
            d += __shfl_xor_sync(0xffffffffu, d, 1);
            if (half == 0 && valid) out[(b*TT + t)*PP + p] = d + b2v;
            av = avn;
        }

        // last MAIN block resets flags for the next graph replay
        __threadfence();
        __syncthreads();
        if (tid == 0) {
            int old = atomicAdd(&f_done, 1);
            if (old == NB_MAIN - 1) {
                atomicExch(&f_xk, 0);
                atomicExch(&f_xw, 0);
                atomicExch(&f_g, 0);
                atomicExch(&f_done, 0);
            }
        }
    }
}

// ---------------------------------------------------------------------------
extern "C" void kernel_launch(void* const* d_in, const int* in_sizes, int n_in,
                              void* d_out, int out_size) {
    const int *pro_id = 0, *label = 0;
    const float *X = 0, *cos_X = 0, *onehot = 0, *Kmat = 0, *rec = 0,
                *bias = 0, *W1 = 0, *b1 = 0, *W2 = 0, *b2 = 0;

    int n_ones = 0;
    for (int i = 0; i < n_in; ++i) if (in_sizes[i] == 1) n_ones++;
    int ones_seen = 0;

    for (int i = 0; i < n_in; ++i) {
        switch (in_sizes[i]) {
            case 800:     if (!pro_id) pro_id = (const int*)d_in[i];
                          else         label  = (const int*)d_in[i];      break;
            case 128000:  X      = (const float*)d_in[i];                 break;
            case 1000000: cos_X  = (const float*)d_in[i];                 break;
            case 10000:   /* trimatrix: tril(ones) hardcoded */           break;
            case 512:     onehot = (const float*)d_in[i];                 break;
            case 65536:   Kmat   = (const float*)d_in[i];                 break;
            case 16384:   rec    = (const float*)d_in[i];                 break;
            case 256:     bias   = (const float*)d_in[i];                 break;
            case 9600:    W1     = (const float*)d_in[i];                 break;
            case 50:      if (!b1) b1 = (const float*)d_in[i];
                          else     W2 = (const float*)d_in[i];            break;
            case 1:       ones_seen++;
                          if (ones_seen == n_ones) b2 = (const float*)d_in[i];
                          break;
            default: break;
        }
    }

    k_all<<<NB_TOT, 256>>>(pro_id, label, X, cos_X, onehot, Kmat, rec,
                           bias, W1, b1, W2, b2, (float*)d_out);
}

// round 8
// speedup vs baseline: 1.3096x; 1.3096x over previous
#include <cuda_runtime.h>

typedef unsigned long long u64t;

#define BB 8
#define TT 100
#define UU 64
#define ZZ 256   // 4U
#define PP 1000
#define NK 50
#define NKP 56   // padded row: [0..24]=k0..24, [25..27]=0, [28..52]=k25..49, [53..55]=0
#define BT (BB*TT) // 800
#define TC 25    // t-chunk size
#define NC 4     // number of chunks

// Scratch (__device__ globals — no allocation)
__device__ __align__(16) float d_xk0[BT*ZZ];     // xt @ kernel, K-half 0 (no bias)
__device__ __align__(16) float d_xk1[BT*ZZ];     // xt @ kernel, K-half 1
__device__ __align__(16) float d_g[BB*TT*NKP];   // ht @ W1[0:64], padded
__device__ __align__(16) float d_XW[1024*NKP];   // X @ W1[64:192] + b1, padded
__device__ __align__(16) float d_A[NC*BB*8*256*28];  // chunk totals (7MB)

// per-quartet sync counters (b*8+pchunk), self-resetting
__device__ int q_arrive[64];
__device__ int q_done[64];

// ---- packed f32x2 helpers ---------------------------------------------------
__device__ __forceinline__ u64t f2pk(float lo, float hi) {
    u64t r; asm("mov.b64 %0,{%1,%2};" : "=l"(r) : "f"(lo), "f"(hi)); return r;
}
__device__ __forceinline__ u64t ffma2(u64t a, u64t b, u64t c) {
    u64t d; asm("fma.rn.f32x2 %0,%1,%2,%3;" : "=l"(d) : "l"(a), "l"(b), "l"(c)); return d;
}
__device__ __forceinline__ u64t fadd2(u64t a, u64t b) {
    u64t d; asm("add.rn.f32x2 %0,%1,%2;" : "=l"(d) : "l"(a), "l"(b)); return d;
}
__device__ __forceinline__ float2 f2up(u64t v) {
    float2 r; asm("mov.b64 {%0,%1},%2;" : "=f"(r.x), "=f"(r.y) : "l"(v)); return r;
}
// hardware tanh (sm_75+): single MUFU op
__device__ __forceinline__ float tanha(float x) {
    float y; asm("tanh.approx.f32 %0, %1;" : "=f"(y) : "f"(x)); return y;
}
__device__ __forceinline__ float siga(float x) {   // sigmoid via tanh identity
    return fmaf(0.5f, tanha(0.5f * x), 0.5f);
}
__device__ __forceinline__ int padpos(int k) { return (k < 25) ? k : k + 3; }

__device__ __forceinline__ int ld_acq(int* p) {
    int v; asm volatile("ld.acquire.gpu.global.s32 %0, [%1];" : "=r"(v) : "l"(p) : "memory");
    return v;
}

// ---------------------------------------------------------------------------
// k_pre: blocks 0..207   -> xk GEMM, K split in 2 halves (64x32 tiles, K=128)
//        blocks 208..332 -> XW[p,:] = X[p,:] @ W1b + b1   (8 p per block)
// ---------------------------------------------------------------------------
__global__ void __launch_bounds__(256) k_pre(
    const int* __restrict__ pro_id, const int* __restrict__ label,
    const float* __restrict__ X, const float* __restrict__ onehot,
    const float* __restrict__ Kmat,
    const float* __restrict__ W1, const float* __restrict__ b1) {
    __shared__ union {
        struct { float A[32][64]; float B[32][32]; } g;
        struct { float W[128*52]; float Xr[8][128]; } w;
    } sh;
    int tid = threadIdx.x;
    int bx = blockIdx.x;

    if (bx < 208) {
        int khalf = bx / 104;
        int sub   = bx % 104;
        int mblk = sub % 13, nblk = sub / 13;
        int rowBase = mblk * 64;
        int n0 = nblk * 32;
        int kbase = khalf * 128;
        float* xkout = khalf ? d_xk1 : d_xk0;
        int ty = tid >> 4, tx = tid & 15;

        int m0 = tid >> 3;
        int kq = (tid & 7) * 4;
        int row0 = rowBase + m0, row1 = rowBase + m0 + 32;
        bool v0 = row0 < BT, v1 = row1 < BT;
        const float *xp0 = 0, *op0 = 0, *xp1 = 0, *op1 = 0;
        if (v0) { xp0 = X + pro_id[row0]*128; op0 = onehot + label[row0]*ZZ; }
        if (v1) { xp1 = X + pro_id[row1]*128; op1 = onehot + label[row1]*ZZ; }

        u64t acc2[2][2] = {{0ull,0ull},{0ull,0ull}};

        for (int k0 = kbase; k0 < kbase + 128; k0 += 32) {
            int i0 = k0 + kq;
            {
                float4 v = make_float4(0.f,0.f,0.f,0.f);
                if (v0) {
                    float4 xv = *(const float4*)&xp0[i0 & 127];
                    float4 ov = *(const float4*)&op0[i0];
                    v = make_float4(xv.x*ov.x, xv.y*ov.y, xv.z*ov.z, xv.w*ov.w);
                }
                sh.g.A[kq+0][m0] = v.x; sh.g.A[kq+1][m0] = v.y;
                sh.g.A[kq+2][m0] = v.z; sh.g.A[kq+3][m0] = v.w;
            }
            {
                float4 v = make_float4(0.f,0.f,0.f,0.f);
                if (v1) {
                    float4 xv = *(const float4*)&xp1[i0 & 127];
                    float4 ov = *(const float4*)&op1[i0];
                    v = make_float4(xv.x*ov.x, xv.y*ov.y, xv.z*ov.z, xv.w*ov.w);
                }
                sh.g.A[kq+0][m0+32] = v.x; sh.g.A[kq+1][m0+32] = v.y;
                sh.g.A[kq+2][m0+32] = v.z; sh.g.A[kq+3][m0+32] = v.w;
            }
            {
                int kk = tid >> 3;
                int n4 = (tid & 7) * 4;
                *(float4*)&sh.g.B[kk][n4] = *(const float4*)&Kmat[(k0 + kk)*256 + n0 + n4];
            }
            __syncthreads();
#pragma unroll
            for (int kk = 0; kk < 32; ++kk) {
                longlong2 av = *(const longlong2*)&sh.g.A[kk][ty*4];
                float2 bv = *(const float2*)&sh.g.B[kk][tx*2];
                u64t bx0 = f2pk(bv.x, bv.x);
                u64t bx1 = f2pk(bv.y, bv.y);
                acc2[0][0] = ffma2((u64t)av.x, bx0, acc2[0][0]);
                acc2[1][0] = ffma2((u64t)av.y, bx0, acc2[1][0]);
                acc2[0][1] = ffma2((u64t)av.x, bx1, acc2[0][1]);
                acc2[1][1] = ffma2((u64t)av.y, bx1, acc2[1][1]);
            }
            __syncthreads();
        }
#pragma unroll
        for (int mp = 0; mp < 2; ++mp) {
            float2 c0 = f2up(acc2[mp][0]);
            float2 c1 = f2up(acc2[mp][1]);
            int r0 = rowBase + ty*4 + 2*mp;
            if (r0 < BT) {
                xkout[r0*ZZ + n0 + tx*2]     = c0.x;
                xkout[r0*ZZ + n0 + tx*2 + 1] = c1.x;
            }
            if (r0 + 1 < BT) {
                xkout[(r0+1)*ZZ + n0 + tx*2]     = c0.y;
                xkout[(r0+1)*ZZ + n0 + tx*2 + 1] = c1.y;
            }
        }
    } else {
        // ---- XW part ----
        int pbase = (bx - 208) * 8;
        for (int idx = tid; idx < 128*NK; idx += 256) {
            int j = idx / NK, k = idx - j*NK;
            sh.w.W[j*52 + k] = __ldg(&W1[(64 + j)*NK + k]);
        }
        {
            int pl = tid >> 5, quad = tid & 31;
            ((float4*)sh.w.Xr[pl])[quad] = *(const float4*)&X[(pbase + pl)*128 + quad*4];
        }
        __syncthreads();

        int pl = tid >> 5, lane = tid & 31;
        int p = pbase + pl;
        if (lane < 25) {
            int k2 = lane * 2;
            u64t acc = f2pk(__ldg(&b1[k2]), __ldg(&b1[k2+1]));
            const float* xr = sh.w.Xr[pl];
#pragma unroll 8
            for (int j = 0; j < 128; ++j) {
                float x = xr[j];
                acc = ffma2(f2pk(x, x), *(const u64t*)&sh.w.W[j*52 + k2], acc);
            }
            float2 r = f2up(acc);
            d_XW[p*NKP + padpos(k2)]     = r.x;
            d_XW[p*NKP + padpos(k2 + 1)] = r.y;
        } else if (lane < 31) {
            int off = (lane <= 27) ? lane : lane + 25;
            d_XW[p*NKP + off] = 0.f;
        }
    }
}

// ---------------------------------------------------------------------------
// k_lstm: one block per batch; thread j owns rec column j (f32x2 packed).
// xk = xk0 + xk1 + bias (K-split recombine). tanh.approx activations.
// h history in shared; epilogue computes g = ht @ W1a.
// ---------------------------------------------------------------------------
__global__ void __launch_bounds__(256) k_lstm(const float* __restrict__ rec,
                                              const float* __restrict__ bias,
                                              const float* __restrict__ W1) {
    int b = blockIdx.x;
    int j = threadIdx.x;
    __shared__ __align__(16) float h_hist[TT][UU];
    __shared__ float a_sh[ZZ];

    u64t rc2[32];
#pragma unroll
    for (int m = 0; m < 32; ++m)
        rc2[m] = f2pk(rec[(2*m)*ZZ + j], rec[(2*m+1)*ZZ + j]);

    float bs = __ldg(&bias[j]);
    int grp = j >> 6;
    float c = 0.f;

    float xA = d_xk0[(b*TT)*ZZ + j];
    float xB = d_xk1[(b*TT)*ZZ + j];

#pragma unroll 1
    for (int t = 0; t < TT; ++t) {
        float xk = xA + xB + bs;
        if (t + 1 < TT) {
            xA = d_xk0[(b*TT + t + 1)*ZZ + j];
            xB = d_xk1[(b*TT + t + 1)*ZZ + j];
        }
        float z;
        if (t == 0) {
            z = xk;
        } else {
            const longlong2* h8 = (const longlong2*)h_hist[t-1];
            u64t z0 = f2pk(xk, 0.f), z1 = 0ull, z2 = 0ull, z3 = 0ull;
#pragma unroll
            for (int i = 0; i < 8; ++i) {
                longlong2 hA = h8[i], hB = h8[i+8];
                z0 = ffma2((u64t)hA.x, rc2[2*i],    z0);
                z1 = ffma2((u64t)hA.y, rc2[2*i+1],  z1);
                z2 = ffma2((u64t)hB.x, rc2[2*i+16], z2);
                z3 = ffma2((u64t)hB.y, rc2[2*i+17], z3);
            }
            float2 r = f2up(fadd2(fadd2(z0, z1), fadd2(z2, z3)));
            z = r.x + r.y;
        }
        a_sh[j] = (grp == 2) ? tanha(z) : siga(z);
        __syncthreads();
        if (j < UU) {
            float ai = a_sh[j], af = a_sh[64+j], ag = a_sh[128+j], ao = a_sh[192+j];
            c = fmaf(af, c, ai*ag);
            h_hist[t][j] = ao * tanha(c);
        }
        __syncthreads();
    }

    // epilogue: g[b,t,k] = sum_u h[t][u] * W1[u*50+k]
    int k = j & 63, tc = j >> 6;
    if (k < NK) {
        u64t w1c[32];
#pragma unroll
        for (int m = 0; m < 32; ++m)
            w1c[m] = f2pk(__ldg(&W1[(2*m)*NK + k]), __ldg(&W1[(2*m+1)*NK + k]));
        int off = padpos(k);
#pragma unroll 1
        for (int tt = tc*25; tt < tc*25 + 25; ++tt) {
            const longlong2* h8 = (const longlong2*)h_hist[tt];
            u64t g0 = 0ull, g1 = 0ull, g2 = 0ull, g3 = 0ull;
#pragma unroll
            for (int i = 0; i < 8; ++i) {
                longlong2 hA = h8[i], hB = h8[i+8];
                g0 = ffma2((u64t)hA.x, w1c[2*i],    g0);
                g1 = ffma2((u64t)hA.y, w1c[2*i+1],  g1);
                g2 = ffma2((u64t)hB.x, w1c[2*i+16], g2);
                g3 = ffma2((u64t)hB.y, w1c[2*i+17], g3);
            }
            float2 r = f2up(fadd2(fadd2(g0, g1), fadd2(g2, g3)));
            d_g[(b*TT + tt)*NKP + off] = r.x + r.y;
        }
    } else if (k < 56) {
        int off = (k >= 53) ? k : (k - 25);
        for (int tt = tc*25; tt < tc*25 + 25; ++tt)
            d_g[(b*TT + tt)*NKP + off] = 0.f;
    }
}

// ---------------------------------------------------------------------------
// k_main: two-level suffix scan. Grid (pchunk=8, b=8, c=4), 256 thr.
// Phase A: chunk totals A_c (c>0). Quartet sync. Phase B: acc = XW + tail,
// local 25-t suffix + relu-dot -> out.
// ---------------------------------------------------------------------------
__global__ void __launch_bounds__(256) k_main(
    const int* __restrict__ pro_id, const float* __restrict__ cosX,
    const float* __restrict__ W2, const float* __restrict__ b2,
    float* __restrict__ out) {
    __shared__ __align__(16) float g_sh[TC*NKP];   // 5.6 KB
    __shared__ int pid_sh[TC];

    int pc8 = blockIdx.x;
    int b   = blockIdx.y;
    int c   = blockIdx.z;
    int tid = threadIdx.x;
    int t0  = c * TC;
    int qidx = b*8 + pc8;

    {   // stage this chunk's g rows + pids
        const float4* gg = (const float4*)&d_g[(b*TT + t0)*NKP];
        float4* gs = (float4*)g_sh;
        for (int i = tid; i < (TC*NKP)/4; i += 256) gs[i] = gg[i];
        if (tid < TC) pid_sh[tid] = pro_id[b*TT + t0 + tid];
    }
    __syncthreads();

    int p    = pc8*128 + (tid >> 1);
    int half = tid & 1;
    bool valid = (p < PP);
    int pc = valid ? p : (PP - 1);

    long aoff = ((long)((c*BB + b)*8 + pc8)*256 + tid) * 28;

    // ---- Phase A: own-chunk total (not needed for c==0) ----
    if (c > 0) {
        float accA[28];
#pragma unroll
        for (int jj = 0; jj < 28; ++jj) accA[jj] = 0.f;
#pragma unroll 1
        for (int tt = 0; tt < TC; ++tt) {
            float av = __ldg(&cosX[pid_sh[tt]*PP + pc]);
            const float4* g4 = (const float4*)&g_sh[tt*NKP + half*28];
#pragma unroll
            for (int m = 0; m < 7; ++m) {
                float4 gv = g4[m];
                accA[4*m]   = fmaf(av, gv.x, accA[4*m]);
                accA[4*m+1] = fmaf(av, gv.y, accA[4*m+1]);
                accA[4*m+2] = fmaf(av, gv.z, accA[4*m+2]);
                accA[4*m+3] = fmaf(av, gv.w, accA[4*m+3]);
            }
        }
        float4* dst = (float4*)&d_A[aoff];
#pragma unroll
        for (int m = 0; m < 7; ++m)
            dst[m] = make_float4(accA[4*m], accA[4*m+1], accA[4*m+2], accA[4*m+3]);
        __threadfence();
    }
    __syncthreads();
    if (tid == 0)
        asm volatile("red.release.gpu.global.add.s32 [%0], 1;" :: "l"(&q_arrive[qidx]) : "memory");

    // ---- preload while waiting ----
    float acc[28], w2r[28];
    {
        const float2* x2 = (const float2*)&d_XW[p*NKP + half*28];
#pragma unroll
        for (int m = 0; m < 14; ++m) { float2 v = x2[m]; acc[2*m] = v.x; acc[2*m+1] = v.y; }
    }
#pragma unroll
    for (int jj = 0; jj < 28; ++jj)
        w2r[jj] = (jj < 25) ? __ldg(&W2[half*25 + jj]) : 0.f;
    float b2v = __ldg(b2);

    // ---- quartet sync ----
    if (tid == 0) {
        while (ld_acq(&q_arrive[qidx]) < 4) __nanosleep(60);
    }
    __syncthreads();

    // ---- tail: sum A of chunks > c ----
    for (int c2 = c + 1; c2 < NC; ++c2) {
        long o2 = ((long)((c2*BB + b)*8 + pc8)*256 + tid) * 28;
        const float4* src = (const float4*)&d_A[o2];
#pragma unroll
        for (int m = 0; m < 7; ++m) {
            float4 v = src[m];
            acc[4*m]   += v.x; acc[4*m+1] += v.y;
            acc[4*m+2] += v.z; acc[4*m+3] += v.w;
        }
    }

    // ---- Phase B: local suffix + relu-dot ----
#pragma unroll 1
    for (int tt = TC - 1; tt >= 0; --tt) {
        float av = __ldg(&cosX[pid_sh[tt]*PP + pc]);
        const float4* g4 = (const float4*)&g_sh[tt*NKP + half*28];
#pragma unroll
        for (int m = 0; m < 7; ++m) {
            float4 gv = g4[m];
            acc[4*m]   = fmaf(av, gv.x, acc[4*m]);
            acc[4*m+1] = fmaf(av, gv.y, acc[4*m+1]);
            acc[4*m+2] = fmaf(av, gv.z, acc[4*m+2]);
            acc[4*m+3] = fmaf(av, gv.w, acc[4*m+3]);
        }
        float d0 = 0.f, d1 = 0.f, d2 = 0.f, d3 = 0.f;
#pragma unroll
        for (int jj = 0; jj < 28; jj += 4) {
            d0 = fmaf(fmaxf(acc[jj],   0.f), w2r[jj],   d0);
            d1 = fmaf(fmaxf(acc[jj+1], 0.f), w2r[jj+1], d1);
            d2 = fmaf(fmaxf(acc[jj+2], 0.f), w2r[jj+2], d2);
            d3 = fmaf(fmaxf(acc[jj+3], 0.f), w2r[jj+3], d3);
        }
        float d = (d0 + d1) + (d2 + d3);
        d += __shfl_xor_sync(0xffffffffu, d, 1);
        if (half == 0 && valid) out[(b*TT + t0 + tt)*PP + p] = d + b2v;
    }

    // ---- counter reset for next graph replay ----
    if (tid == 0) {
        int old = atomicAdd(&q_done[qidx], 1);
        if (old == 3) {
            atomicExch(&q_arrive[qidx], 0);
            atomicExch(&q_done[qidx], 0);
        }
    }
}

// ---------------------------------------------------------------------------
extern "C" void kernel_launch(void* const* d_in, const int* in_sizes, int n_in,
                              void* d_out, int out_size) {
    const int *pro_id = 0, *label = 0;
    const float *X = 0, *cos_X = 0, *onehot = 0, *Kmat = 0, *rec = 0,
                *bias = 0, *W1 = 0, *b1 = 0, *W2 = 0, *b2 = 0;

    int n_ones = 0;
    for (int i = 0; i < n_in; ++i) if (in_sizes[i] == 1) n_ones++;
    int ones_seen = 0;

    for (int i = 0; i < n_in; ++i) {
        switch (in_sizes[i]) {
            case 800:     if (!pro_id) pro_id = (const int*)d_in[i];
                          else         label  = (const int*)d_in[i];      break;
            case 128000:  X      = (const float*)d_in[i];                 break;
            case 1000000: cos_X  = (const float*)d_in[i];                 break;
            case 10000:   /* trimatrix: tril(ones) hardcoded */           break;
            case 512:     onehot = (const float*)d_in[i];                 break;
            case 65536:   Kmat   = (const float*)d_in[i];                 break;
            case 16384:   rec    = (const float*)d_in[i];                 break;
            case 256:     bias   = (const float*)d_in[i];                 break;
            case 9600:    W1     = (const float*)d_in[i];                 break;
            case 50:      if (!b1) b1 = (const float*)d_in[i];
                          else     W2 = (const float*)d_in[i];            break;
            case 1:       ones_seen++;
                          if (ones_seen == n_ones) b2 = (const float*)d_in[i];
                          break;
            default: break;
        }
    }

    float* out = (float*)d_out;

    k_pre <<<333, 256>>>(pro_id, label, X, onehot, Kmat, W1, b1);
    k_lstm<<<BB, 256>>>(rec, bias, W1);
    k_main<<<dim3(8, BB, NC), 256>>>(pro_id, cos_X, W2, b2, out);
}

// round 9
// speedup vs baseline: 1.3394x; 1.0228x over previous
#include <cuda_runtime.h>

typedef unsigned long long u64t;

#define BB 8
#define TT 100
#define UU 64
#define ZZ 256   // 4U
#define PP 1000
#define NK 50
#define NKP 56   // padded row: [0..24]=k0..24, [25..27]=0, [28..52]=k25..49, [53..55]=0
#define BT (BB*TT) // 800
#define TC 20    // t-chunk size
#define NC 5     // number of chunks
#define KQ 4     // GEMM K-split factor

// Scratch (__device__ globals — no allocation)
__device__ __align__(16) float d_xkq[KQ*BT*ZZ];  // xt @ kernel, 4 K-quarters (no bias)
__device__ __align__(16) float d_g[BB*TT*NKP];   // ht @ W1[0:64], padded
__device__ __align__(16) float d_XW[1024*NKP];   // X @ W1[64:192] + b1, padded
__device__ __align__(16) float d_A[NC*BB*8*256*28];  // chunk totals

// per-(b,pchunk) sync counters, self-resetting
__device__ int q_arrive[64];
__device__ int q_done[64];

// ---- packed f32x2 helpers ---------------------------------------------------
__device__ __forceinline__ u64t f2pk(float lo, float hi) {
    u64t r; asm("mov.b64 %0,{%1,%2};" : "=l"(r) : "f"(lo), "f"(hi)); return r;
}
__device__ __forceinline__ u64t ffma2(u64t a, u64t b, u64t c) {
    u64t d; asm("fma.rn.f32x2 %0,%1,%2,%3;" : "=l"(d) : "l"(a), "l"(b), "l"(c)); return d;
}
__device__ __forceinline__ u64t fadd2(u64t a, u64t b) {
    u64t d; asm("add.rn.f32x2 %0,%1,%2;" : "=l"(d) : "l"(a), "l"(b)); return d;
}
__device__ __forceinline__ float2 f2up(u64t v) {
    float2 r; asm("mov.b64 {%0,%1},%2;" : "=f"(r.x), "=f"(r.y) : "l"(v)); return r;
}
__device__ __forceinline__ float tanha(float x) {
    float y; asm("tanh.approx.f32 %0, %1;" : "=f"(y) : "f"(x)); return y;
}
__device__ __forceinline__ float siga(float x) {
    return fmaf(0.5f, tanha(0.5f * x), 0.5f);
}
__device__ __forceinline__ int padpos(int k) { return (k < 25) ? k : k + 3; }

__device__ __forceinline__ int ld_acq(int* p) {
    int v; asm volatile("ld.acquire.gpu.global.s32 %0, [%1];" : "=r"(v) : "l"(p) : "memory");
    return v;
}

// ---------------------------------------------------------------------------
// k_pre: blocks 0..415   -> xk GEMM, K split in 4 quarters (64x32 tiles, K=64)
//        blocks 416..540 -> XW[p,:] = X[p,:] @ W1b + b1  (8 p per block)
// ---------------------------------------------------------------------------
__global__ void __launch_bounds__(256) k_pre(
    const int* __restrict__ pro_id, const int* __restrict__ label,
    const float* __restrict__ X, const float* __restrict__ onehot,
    const float* __restrict__ Kmat,
    const float* __restrict__ W1, const float* __restrict__ b1) {
    __shared__ union {
        struct { float A[32][64]; float B[32][32]; } g;
        struct { float W[128*52]; float Xr[8][128]; } w;
    } sh;
    int tid = threadIdx.x;
    int bx = blockIdx.x;

    if (bx < 104*KQ) {
        int kquart = bx / 104;
        int sub    = bx % 104;
        int mblk = sub % 13, nblk = sub / 13;
        int rowBase = mblk * 64;
        int n0 = nblk * 32;
        int kbase = kquart * 64;
        float* xkout = d_xkq + kquart*BT*ZZ;
        int ty = tid >> 4, tx = tid & 15;

        int m0 = tid >> 3;
        int kq = (tid & 7) * 4;
        int row0 = rowBase + m0, row1 = rowBase + m0 + 32;
        bool v0 = row0 < BT, v1 = row1 < BT;
        const float *xp0 = 0, *op0 = 0, *xp1 = 0, *op1 = 0;
        if (v0) { xp0 = X + pro_id[row0]*128; op0 = onehot + label[row0]*ZZ; }
        if (v1) { xp1 = X + pro_id[row1]*128; op1 = onehot + label[row1]*ZZ; }

        u64t acc2[2][2] = {{0ull,0ull},{0ull,0ull}};

        for (int k0 = kbase; k0 < kbase + 64; k0 += 32) {
            int i0 = k0 + kq;
            {
                float4 v = make_float4(0.f,0.f,0.f,0.f);
                if (v0) {
                    float4 xv = *(const float4*)&xp0[i0 & 127];
                    float4 ov = *(const float4*)&op0[i0];
                    v = make_float4(xv.x*ov.x, xv.y*ov.y, xv.z*ov.z, xv.w*ov.w);
                }
                sh.g.A[kq+0][m0] = v.x; sh.g.A[kq+1][m0] = v.y;
                sh.g.A[kq+2][m0] = v.z; sh.g.A[kq+3][m0] = v.w;
            }
            {
                float4 v = make_float4(0.f,0.f,0.f,0.f);
                if (v1) {
                    float4 xv = *(const float4*)&xp1[i0 & 127];
                    float4 ov = *(const float4*)&op1[i0];
                    v = make_float4(xv.x*ov.x, xv.y*ov.y, xv.z*ov.z, xv.w*ov.w);
                }
                sh.g.A[kq+0][m0+32] = v.x; sh.g.A[kq+1][m0+32] = v.y;
                sh.g.A[kq+2][m0+32] = v.z; sh.g.A[kq+3][m0+32] = v.w;
            }
            {
                int kk = tid >> 3;
                int n4 = (tid & 7) * 4;
                *(float4*)&sh.g.B[kk][n4] = *(const float4*)&Kmat[(k0 + kk)*256 + n0 + n4];
            }
            __syncthreads();
#pragma unroll
            for (int kk = 0; kk < 32; ++kk) {
                longlong2 av = *(const longlong2*)&sh.g.A[kk][ty*4];
                float2 bv = *(const float2*)&sh.g.B[kk][tx*2];
                u64t bx0 = f2pk(bv.x, bv.x);
                u64t bx1 = f2pk(bv.y, bv.y);
                acc2[0][0] = ffma2((u64t)av.x, bx0, acc2[0][0]);
                acc2[1][0] = ffma2((u64t)av.y, bx0, acc2[1][0]);
                acc2[0][1] = ffma2((u64t)av.x, bx1, acc2[0][1]);
                acc2[1][1] = ffma2((u64t)av.y, bx1, acc2[1][1]);
            }
            __syncthreads();
        }
#pragma unroll
        for (int mp = 0; mp < 2; ++mp) {
            float2 c0 = f2up(acc2[mp][0]);
            float2 c1 = f2up(acc2[mp][1]);
            int r0 = rowBase + ty*4 + 2*mp;
            if (r0 < BT) {
                xkout[r0*ZZ + n0 + tx*2]     = c0.x;
                xkout[r0*ZZ + n0 + tx*2 + 1] = c1.x;
            }
            if (r0 + 1 < BT) {
                xkout[(r0+1)*ZZ + n0 + tx*2]     = c0.y;
                xkout[(r0+1)*ZZ + n0 + tx*2 + 1] = c1.y;
            }
        }
    } else {
        // ---- XW part ----
        int pbase = (bx - 104*KQ) * 8;
        for (int idx = tid; idx < 128*NK; idx += 256) {
            int j = idx / NK, k = idx - j*NK;
            sh.w.W[j*52 + k] = __ldg(&W1[(64 + j)*NK + k]);
        }
        {
            int pl = tid >> 5, quad = tid & 31;
            ((float4*)sh.w.Xr[pl])[quad] = *(const float4*)&X[(pbase + pl)*128 + quad*4];
        }
        __syncthreads();

        int pl = tid >> 5, lane = tid & 31;
        int p = pbase + pl;
        if (lane < 25) {
            int k2 = lane * 2;
            u64t acc = f2pk(__ldg(&b1[k2]), __ldg(&b1[k2+1]));
            const float* xr = sh.w.Xr[pl];
#pragma unroll 8
            for (int j = 0; j < 128; ++j) {
                float x = xr[j];
                acc = ffma2(f2pk(x, x), *(const u64t*)&sh.w.W[j*52 + k2], acc);
            }
            float2 r = f2up(acc);
            d_XW[p*NKP + padpos(k2)]     = r.x;
            d_XW[p*NKP + padpos(k2 + 1)] = r.y;
        } else if (lane < 31) {
            int off = (lane <= 27) ? lane : lane + 25;
            d_XW[p*NKP + off] = 0.f;
        }
    }
}

// ---------------------------------------------------------------------------
// k_lstm: one block per batch; thread j owns rec column j (f32x2 packed).
// xk = sum of 4 K-quarter partials + bias. tanh.approx activations.
// ---------------------------------------------------------------------------
__global__ void __launch_bounds__(256) k_lstm(const float* __restrict__ rec,
                                              const float* __restrict__ bias,
                                              const float* __restrict__ W1) {
    int b = blockIdx.x;
    int j = threadIdx.x;
    __shared__ __align__(16) float h_hist[TT][UU];
    __shared__ float a_sh[ZZ];

    u64t rc2[32];
#pragma unroll
    for (int m = 0; m < 32; ++m)
        rc2[m] = f2pk(rec[(2*m)*ZZ + j], rec[(2*m+1)*ZZ + j]);

    float bs = __ldg(&bias[j]);
    int grp = j >> 6;
    float c = 0.f;

    const float* xq = d_xkq + b*TT*ZZ + j;
    float xs;
    {
        float a0 = xq[0];
        float a1 = xq[BT*ZZ];
        float a2 = xq[2*BT*ZZ];
        float a3 = xq[3*BT*ZZ];
        xs = ((a0 + a1) + (a2 + a3)) + bs;
    }

#pragma unroll 1
    for (int t = 0; t < TT; ++t) {
        float xk = xs;
        float n0v = 0.f, n1v = 0.f, n2v = 0.f, n3v = 0.f;
        if (t + 1 < TT) {
            int o = (t + 1) * ZZ;
            n0v = xq[o];
            n1v = xq[o + BT*ZZ];
            n2v = xq[o + 2*BT*ZZ];
            n3v = xq[o + 3*BT*ZZ];
        }
        float z;
        if (t == 0) {
            z = xk;
        } else {
            const longlong2* h8 = (const longlong2*)h_hist[t-1];
            u64t z0 = f2pk(xk, 0.f), z1 = 0ull, z2 = 0ull, z3 = 0ull;
#pragma unroll
            for (int i = 0; i < 8; ++i) {
                longlong2 hA = h8[i], hB = h8[i+8];
                z0 = ffma2((u64t)hA.x, rc2[2*i],    z0);
                z1 = ffma2((u64t)hA.y, rc2[2*i+1],  z1);
                z2 = ffma2((u64t)hB.x, rc2[2*i+16], z2);
                z3 = ffma2((u64t)hB.y, rc2[2*i+17], z3);
            }
            float2 r = f2up(fadd2(fadd2(z0, z1), fadd2(z2, z3)));
            z = r.x + r.y;
        }
        a_sh[j] = (grp == 2) ? tanha(z) : siga(z);
        __syncthreads();
        if (j < UU) {
            float ai = a_sh[j], af = a_sh[64+j], ag = a_sh[128+j], ao = a_sh[192+j];
            c = fmaf(af, c, ai*ag);
            h_hist[t][j] = ao * tanha(c);
        }
        __syncthreads();
        xs = ((n0v + n1v) + (n2v + n3v)) + bs;
    }

    // epilogue: g[b,t,k] = sum_u h[t][u] * W1[u*50+k]
    int k = j & 63, tc = j >> 6;
    if (k < NK) {
        u64t w1c[32];
#pragma unroll
        for (int m = 0; m < 32; ++m)
            w1c[m] = f2pk(__ldg(&W1[(2*m)*NK + k]), __ldg(&W1[(2*m+1)*NK + k]));
        int off = padpos(k);
#pragma unroll 1
        for (int tt = tc*25; tt < tc*25 + 25; ++tt) {
            const longlong2* h8 = (const longlong2*)h_hist[tt];
            u64t g0 = 0ull, g1 = 0ull, g2 = 0ull, g3 = 0ull;
#pragma unroll
            for (int i = 0; i < 8; ++i) {
                longlong2 hA = h8[i], hB = h8[i+8];
                g0 = ffma2((u64t)hA.x, w1c[2*i],    g0);
                g1 = ffma2((u64t)hA.y, w1c[2*i+1],  g1);
                g2 = ffma2((u64t)hB.x, w1c[2*i+16], g2);
                g3 = ffma2((u64t)hB.y, w1c[2*i+17], g3);
            }
            float2 r = f2up(fadd2(fadd2(g0, g1), fadd2(g2, g3)));
            d_g[(b*TT + tt)*NKP + off] = r.x + r.y;
        }
    } else if (k < 56) {
        int off = (k >= 53) ? k : (k - 25);
        for (int tt = tc*25; tt < tc*25 + 25; ++tt)
            d_g[(b*TT + tt)*NKP + off] = 0.f;
    }
}

// ---------------------------------------------------------------------------
// k_main: two-level suffix scan, packed f32x2. Grid (pchunk=8, b=8, c=5).
// ---------------------------------------------------------------------------
__global__ void __launch_bounds__(256) k_main(
    const int* __restrict__ pro_id, const float* __restrict__ cosX,
    const float* __restrict__ W2, const float* __restrict__ b2,
    float* __restrict__ out) {
    __shared__ __align__(16) float g_sh[TC*NKP];
    __shared__ int pid_sh[TC];

    int pc8 = blockIdx.x;
    int b   = blockIdx.y;
    int c   = blockIdx.z;
    int tid = threadIdx.x;
    int t0  = c * TC;
    int qidx = b*8 + pc8;

    {
        const float4* gg = (const float4*)&d_g[(b*TT + t0)*NKP];
        float4* gs = (float4*)g_sh;
        for (int i = tid; i < (TC*NKP)/4; i += 256) gs[i] = gg[i];
        if (tid < TC) pid_sh[tid] = pro_id[b*TT + t0 + tid];
    }
    __syncthreads();

    int p    = pc8*128 + (tid >> 1);
    int half = tid & 1;
    bool valid = (p < PP);
    int pc = valid ? p : (PP - 1);

    long aoff = ((long)((c*BB + b)*8 + pc8)*256 + tid) * 28;

    // ---- Phase A: own-chunk total (c>0 only), packed ----
    if (c > 0) {
        u64t accA[14];
#pragma unroll
        for (int m = 0; m < 14; ++m) accA[m] = 0ull;
#pragma unroll 1
        for (int tt = 0; tt < TC; ++tt) {
            float av = __ldg(&cosX[pid_sh[tt]*PP + pc]);
            u64t av2 = f2pk(av, av);
            const longlong2* g2 = (const longlong2*)&g_sh[tt*NKP + half*28];
#pragma unroll
            for (int m = 0; m < 7; ++m) {
                longlong2 gv = g2[m];
                accA[2*m]   = ffma2(av2, (u64t)gv.x, accA[2*m]);
                accA[2*m+1] = ffma2(av2, (u64t)gv.y, accA[2*m+1]);
            }
        }
        longlong2* dst = (longlong2*)&d_A[aoff];
#pragma unroll
        for (int m = 0; m < 7; ++m)
            dst[m] = make_longlong2((long long)accA[2*m], (long long)accA[2*m+1]);
        __threadfence();
    }
    __syncthreads();
    if (tid == 0)
        asm volatile("red.release.gpu.global.add.s32 [%0], 1;" :: "l"(&q_arrive[qidx]) : "memory");

    // ---- preload while waiting ----
    u64t acc[14];
    float w2r[28];
    {
        const longlong2* x2 = (const longlong2*)&d_XW[p*NKP + half*28];
#pragma unroll
        for (int m = 0; m < 7; ++m) {
            longlong2 v = x2[m];
            acc[2*m] = (u64t)v.x; acc[2*m+1] = (u64t)v.y;
        }
    }
#pragma unroll
    for (int jj = 0; jj < 28; ++jj)
        w2r[jj] = (jj < 25) ? __ldg(&W2[half*25 + jj]) : 0.f;
    float b2v = __ldg(b2);

    // ---- wait for all chunks of this (b,pchunk) ----
    if (tid == 0) {
        while (ld_acq(&q_arrive[qidx]) < NC) __nanosleep(60);
    }
    __syncthreads();

    // ---- tail: sum A of chunks > c ----
    for (int c2 = c + 1; c2 < NC; ++c2) {
        long o2 = ((long)((c2*BB + b)*8 + pc8)*256 + tid) * 28;
        const longlong2* src = (const longlong2*)&d_A[o2];
#pragma unroll
        for (int m = 0; m < 7; ++m) {
            longlong2 v = src[m];
            acc[2*m]   = fadd2(acc[2*m],   (u64t)v.x);
            acc[2*m+1] = fadd2(acc[2*m+1], (u64t)v.y);
        }
    }

    // ---- Phase B: local suffix + relu-dot ----
#pragma unroll 1
    for (int tt = TC - 1; tt >= 0; --tt) {
        float av = __ldg(&cosX[pid_sh[tt]*PP + pc]);
        u64t av2 = f2pk(av, av);
        const longlong2* g2 = (const longlong2*)&g_sh[tt*NKP + half*28];
#pragma unroll
        for (int m = 0; m < 7; ++m) {
            longlong2 gv = g2[m];
            acc[2*m]   = ffma2(av2, (u64t)gv.x, acc[2*m]);
            acc[2*m+1] = ffma2(av2, (u64t)gv.y, acc[2*m+1]);
        }
        float d0 = 0.f, d1 = 0.f, d2 = 0.f, d3 = 0.f;
#pragma unroll
        for (int m = 0; m < 7; ++m) {
            float2 a0 = f2up(acc[2*m]);
            float2 a1 = f2up(acc[2*m+1]);
            d0 = fmaf(fmaxf(a0.x, 0.f), w2r[4*m],   d0);
            d1 = fmaf(fmaxf(a0.y, 0.f), w2r[4*m+1], d1);
            d2 = fmaf(fmaxf(a1.x, 0.f), w2r[4*m+2], d2);
            d3 = fmaf(fmaxf(a1.y, 0.f), w2r[4*m+3], d3);
        }
        float d = (d0 + d1) + (d2 + d3);
        d += __shfl_xor_sync(0xffffffffu, d, 1);
        if (half == 0 && valid) out[(b*TT + t0 + tt)*PP + p] = d + b2v;
    }

    // ---- counter reset for next graph replay ----
    if (tid == 0) {
        int old = atomicAdd(&q_done[qidx], 1);
        if (old == NC - 1) {
            atomicExch(&q_arrive[qidx], 0);
            atomicExch(&q_done[qidx], 0);
        }
    }
}

// ---------------------------------------------------------------------------
extern "C" void kernel_launch(void* const* d_in, const int* in_sizes, int n_in,
                              void* d_out, int out_size) {
    const int *pro_id = 0, *label = 0;
    const float *X = 0, *cos_X = 0, *onehot = 0, *Kmat = 0, *rec = 0,
                *bias = 0, *W1 = 0, *b1 = 0, *W2 = 0, *b2 = 0;

    int n_ones = 0;
    for (int i = 0; i < n_in; ++i) if (in_sizes[i] == 1) n_ones++;
    int ones_seen = 0;

    for (int i = 0; i < n_in; ++i) {
        switch (in_sizes[i]) {
            case 800:     if (!pro_id) pro_id = (const int*)d_in[i];
                          else         label  = (const int*)d_in[i];      break;
            case 128000:  X      = (const float*)d_in[i];                 break;
            case 1000000: cos_X  = (const float*)d_in[i];                 break;
            case 10000:   /* trimatrix: tril(ones) hardcoded */           break;
            case 512:     onehot = (const float*)d_in[i];                 break;
            case 65536:   Kmat   = (const float*)d_in[i];                 break;
            case 16384:   rec    = (const float*)d_in[i];                 break;
            case 256:     bias   = (const float*)d_in[i];                 break;
            case 9600:    W1     = (const float*)d_in[i];                 break;
            case 50:      if (!b1) b1 = (const float*)d_in[i];
                          else     W2 = (const float*)d_in[i];            break;
            case 1:       ones_seen++;
                          if (ones_seen == n_ones) b2 = (const float*)d_in[i];
                          break;
            default: break;
        }
    }

    float* out = (float*)d_out;

    k_pre <<<104*KQ + 125, 256>>>(pro_id, label, X, onehot, Kmat, W1, b1);
    k_lstm<<<BB, 256>>>(rec, bias, W1);
    k_main<<<dim3(8, BB, NC), 256>>>(pro_id, cos_X, W2, b2, out);
}